// round 17
// baseline (speedup 1.0000x reference)
#include <cuda_runtime.h>
#include <cuda_bf16.h>

typedef unsigned int u32;
typedef unsigned long long u64;

#define N_ROWS 2048
#define K_CODES 81920
#define C_DIM 64
#define M_TILE 128
#define N_TILE 128
#define CHUNK 1024
#define TILES (CHUNK / N_TILE)     // 8
#define NCHUNKS (K_CODES / CHUNK)  // 80
#define NCHUNKS_SEED 18            // seed pass: codes 0..18431, one full wave
#define PITCHB 144                 // bytes per smem row (72 bf16, conflict-free)
#define CAP 4096
#define PREP_ROWS 128
#define PREP_PITCH 68

// ---------------- device scratch (no allocation allowed) -------------------
__device__ __nv_bfloat16 g_zbf[N_ROWS * C_DIM];
__device__ __nv_bfloat16 g_ebf[K_CODES * C_DIM];
__device__ float g_enorm[K_CODES];
__device__ float g_znorm[N_ROWS];
__device__ float g_sumabs[N_ROWS];
__device__ u32 g_smin[N_ROWS];     // orderable-uint float (monotone decreasing)
__device__ u32 g_emax;             // bits of max|emb|
__device__ int g_cnt[N_ROWS];
__device__ int g_cand[N_ROWS * CAP];
__device__ double g_rowloss[N_ROWS];
__device__ u32 g_done_ctr;         // rescore completion counter (reset in prep)

// ---------------- helpers ---------------------------------------------------
__device__ __forceinline__ u32 f2o(float f) {
    u32 b = __float_as_uint(f);
    return (b & 0x80000000u) ? ~b : (b | 0x80000000u);
}
__device__ __forceinline__ float o2f(u32 o) {
    u32 b = (o & 0x80000000u) ? (o ^ 0x80000000u) : ~o;
    return __uint_as_float(b);
}
__device__ __forceinline__ u32 smem_u32(const void* p) {
    u32 a; asm("{ .reg .u64 t; cvta.to.shared.u64 t, %1; cvt.u32.u64 %0, t; }"
               : "=r"(a) : "l"(p));
    return a;
}
__device__ __forceinline__ void cpa16(u32 dst, const void* src) {
    asm volatile("cp.async.cg.shared.global [%0], [%1], 16;" :: "r"(dst), "l"(src));
}
__device__ __forceinline__ void cpa_commit() { asm volatile("cp.async.commit_group;"); }
template <int N> __device__ __forceinline__ void cpa_wait() {
    asm volatile("cp.async.wait_group %0;" :: "n"(N));
}
__device__ __forceinline__ void ldsm4(u32* r, u32 addr) {
    asm volatile("ldmatrix.sync.aligned.m8n8.x4.shared.b16 {%0,%1,%2,%3}, [%4];"
                 : "=r"(r[0]), "=r"(r[1]), "=r"(r[2]), "=r"(r[3]) : "r"(addr));
}
__device__ __forceinline__ void mma16816(float* d, const u32* a, u32 b0, u32 b1) {
    asm volatile(
        "mma.sync.aligned.m16n8k16.row.col.f32.bf16.bf16.f32 "
        "{%0,%1,%2,%3},{%4,%5,%6,%7},{%8,%9},{%0,%1,%2,%3};"
        : "+f"(d[0]), "+f"(d[1]), "+f"(d[2]), "+f"(d[3])
        : "r"(a[0]), "r"(a[1]), "r"(a[2]), "r"(a[3]), "r"(b0), "r"(b1));
}

// ---------------------------------------------------------------------------
// Prep v3 — R16 VERBATIM + g_done_ctr reset (graph-replay-safe).
// ---------------------------------------------------------------------------
__global__ __launch_bounds__(256) void vq_prep(const float* __restrict__ z,
                                               const float* __restrict__ emb) {
    __shared__ float sZ[PREP_ROWS * PREP_PITCH];
    __shared__ float sMax[256];
    const int tid = threadIdx.x;
    if (blockIdx.x == 0 && tid == 0) g_done_ctr = 0;
    const bool isE = blockIdx.x < (K_CODES / PREP_ROWS);
    const int rowBase = isE ? blockIdx.x * PREP_ROWS
                            : (blockIdx.x - K_CODES / PREP_ROWS) * PREP_ROWS;
    const float* src = isE ? emb : z;

    float lmax = 0.f;
#pragma unroll
    for (int j = 0; j < 8; ++j) {
        int f = tid + 256 * j;
        int r = f >> 4, c4 = f & 15;
        float4 v = *reinterpret_cast<const float4*>(
            src + (size_t)(rowBase + r) * C_DIM + c4 * 4);
        sZ[r * PREP_PITCH + c4 * 4 + 0] = v.x;
        sZ[r * PREP_PITCH + c4 * 4 + 1] = v.y;
        sZ[r * PREP_PITCH + c4 * 4 + 2] = v.z;
        sZ[r * PREP_PITCH + c4 * 4 + 3] = v.w;
        if (isE)
            lmax = fmaxf(lmax, fmaxf(fmaxf(fabsf(v.x), fabsf(v.y)),
                                     fmaxf(fabsf(v.z), fabsf(v.w))));
    }
    __syncthreads();

    if (tid < PREP_ROWS) {
        const float* row = sZ + tid * PREP_PITCH;
        if (isE) {
            float s = 0.f;
#pragma unroll
            for (int c = 0; c < C_DIM; ++c) {
                float v = row[c];
                s = fmaf(v, v, s);
            }
            g_enorm[rowBase + tid] = s;
        } else {
            float s = 0.f, sa = 0.f;
#pragma unroll
            for (int c = 0; c < C_DIM; ++c) {
                float v = row[c];
                s = fmaf(v, v, s);
                sa += fabsf(v);
            }
            g_znorm[rowBase + tid] = s;
            g_sumabs[rowBase + tid] = sa;
            g_smin[rowBase + tid] = 0xFFFFFFFFu;
            g_cnt[rowBase + tid] = 0;
        }
    }

    u64* dst = isE ? reinterpret_cast<u64*>(g_ebf) + (size_t)rowBase * 16
                   : reinterpret_cast<u64*>(g_zbf) + (size_t)rowBase * 16;
#pragma unroll
    for (int j = 0; j < 8; ++j) {
        int f = tid + 256 * j;
        int r = f >> 4, c4 = f & 15;
        const float* p = sZ + r * PREP_PITCH + c4 * 4;
        __nv_bfloat162 p0 = {__float2bfloat16_rn(p[0]), __float2bfloat16_rn(p[1])};
        __nv_bfloat162 p1 = {__float2bfloat16_rn(p[2]), __float2bfloat16_rn(p[3])};
        u64 pk = ((u64)*reinterpret_cast<u32*>(&p1) << 32)
               | *reinterpret_cast<u32*>(&p0);
        dst[f] = pk;
    }

    sMax[tid] = lmax;
    __syncthreads();
#pragma unroll
    for (int st = 128; st >= 1; st >>= 1) {
        if (tid < st) sMax[tid] = fmaxf(sMax[tid], sMax[tid + st]);
        __syncthreads();
    }
    if (tid == 0 && sMax[0] > 0.f) atomicMax(&g_emax, __float_as_uint(sMax[0]));
}

// ---------------------------------------------------------------------------
// bf16 HMMA filter — R16 VERBATIM.
// ---------------------------------------------------------------------------
__global__ __launch_bounds__(256, 2) void vq_mma_pass(int pass) {
    extern __shared__ char smem[];
    const u32 sbase = smem_u32(smem);
    float* sMar = (float*)(smem + 56320);
    float* sThr = (float*)(smem + 56832);
    float* sMin = (float*)(smem + 56320);

    const int tid = threadIdx.x, lane = tid & 31, wid = tid >> 5;
    const int warp_m = wid >> 1, warp_n = wid & 1;
    const int g = lane >> 2, tq = lane & 3;
    const int rowBase = blockIdx.x * M_TILE;
    const int kChunk = blockIdx.y * CHUNK;

#pragma unroll
    for (int j = 0; j < 4; ++j) {
        int idx = tid + 256 * j, r = idx >> 3, sg = idx & 7;
        cpa16(sbase + r * PITCHB + sg * 16,
              g_zbf + (size_t)(rowBase + r) * C_DIM + sg * 8);
        cpa16(sbase + 18432 + r * PITCHB + sg * 16,
              g_ebf + (size_t)(kChunk + r) * C_DIM + sg * 8);
    }
    if (tid < 32) cpa16(sbase + 55296 + tid * 16, g_enorm + kChunk + tid * 4);
    cpa_commit();

    if (pass && tid < M_TILE) {
        int r = rowBase + tid;
        sMar[tid] = 4.0f * 0.0082f * __uint_as_float(g_emax) * g_sumabs[r]
                  + g_znorm[r] * 3.0e-7f + 2e-6f;
    }

    float runmin[2][2];
#pragma unroll
    for (int am = 0; am < 2; ++am)
#pragma unroll
        for (int h = 0; h < 2; ++h) runmin[am][h] = __int_as_float(0x7F800000);

    u32 aoff[2];
#pragma unroll
    for (int am = 0; am < 2; ++am)
        aoff[am] = sbase + (u32)(warp_m * 32 + am * 16 + (lane & 15)) * PITCHB
                 + ((lane >> 4) & 1) * 16;
    const u32 boffl = (u32)(warp_n * 64 + ((lane >> 4) << 3) + (lane & 7)) * PITCHB
                    + ((lane >> 3) & 1) * 16;

    for (int t = 0; t < TILES; ++t) {
        int buf = t & 1;
        if (t + 1 < TILES) {
            u32 db = sbase + (((t + 1) & 1) ? 36864u : 18432u);
            const __nv_bfloat16* src =
                g_ebf + (size_t)(kChunk + (t + 1) * N_TILE) * C_DIM;
#pragma unroll
            for (int j = 0; j < 4; ++j) {
                int idx = tid + 256 * j, r = idx >> 3, sg = idx & 7;
                cpa16(db + r * PITCHB + sg * 16, src + (size_t)r * C_DIM + sg * 8);
            }
            if (tid < 32)
                cpa16(sbase + (((t + 1) & 1) ? 55808u : 55296u) + tid * 16,
                      g_enorm + kChunk + (t + 1) * N_TILE + tid * 4);
            cpa_commit();
            cpa_wait<1>();
        } else {
            cpa_wait<0>();
        }

        if (pass && tid < M_TILE)
            sThr[tid] = o2f(__ldcg(&g_smin[rowBase + tid])) + sMar[tid];
        __syncthreads();

        const u32 Bb = sbase + (buf ? 36864u : 18432u);
        const float* En = (const float*)(smem + (buf ? 55808 : 55296));

        float d[2][8][4];
#pragma unroll
        for (int am = 0; am < 2; ++am)
#pragma unroll
            for (int bn = 0; bn < 8; ++bn)
#pragma unroll
                for (int e = 0; e < 4; ++e) d[am][bn][e] = 0.f;

#pragma unroll
        for (int ks = 0; ks < 4; ++ks) {
            u32 aa[2][4];
            ldsm4(aa[0], aoff[0] + ks * 32);
            ldsm4(aa[1], aoff[1] + ks * 32);
#pragma unroll
            for (int bp = 0; bp < 4; ++bp) {
                u32 bb[4];
                ldsm4(bb, Bb + boffl + bp * (16 * PITCHB) + ks * 32);
                mma16816(d[0][2 * bp],     aa[0], bb[0], bb[1]);
                mma16816(d[0][2 * bp + 1], aa[0], bb[2], bb[3]);
                mma16816(d[1][2 * bp],     aa[1], bb[0], bb[1]);
                mma16816(d[1][2 * bp + 1], aa[1], bb[2], bb[3]);
            }
        }

        if (!pass) {
#pragma unroll
            for (int am = 0; am < 2; ++am)
#pragma unroll
                for (int bn = 0; bn < 8; ++bn)
#pragma unroll
                    for (int e = 0; e < 4; ++e) {
                        int col = warp_n * 64 + bn * 8 + 2 * tq + (e & 1);
                        float s = __fsub_rn(En[col],
                                            __fmul_rn(2.0f, d[am][bn][e]));
                        runmin[am][e >> 1] = fminf(runmin[am][e >> 1], s);
                    }
        } else {
            float thrv[2][2];
#pragma unroll
            for (int am = 0; am < 2; ++am)
#pragma unroll
                for (int h = 0; h < 2; ++h)
                    thrv[am][h] = sThr[warp_m * 32 + am * 16 + g + 8 * h];
#pragma unroll
            for (int am = 0; am < 2; ++am)
#pragma unroll
                for (int bn = 0; bn < 8; ++bn)
#pragma unroll
                    for (int e = 0; e < 4; ++e) {
                        int col = warp_n * 64 + bn * 8 + 2 * tq + (e & 1);
                        int h = e >> 1;
                        float s = __fsub_rn(En[col],
                                            __fmul_rn(2.0f, d[am][bn][e]));
                        runmin[am][h] = fminf(runmin[am][h], s);
                        if (s <= thrv[am][h]) {
                            int row = rowBase + warp_m * 32 + am * 16 + g + 8 * h;
                            int k = kChunk + t * N_TILE + col;
                            int ix = atomicAdd(&g_cnt[row], 1);
                            if (ix < CAP) g_cand[(size_t)row * CAP + ix] = k;
                        }
                    }
        }
        __syncthreads();
    }

#pragma unroll
    for (int am = 0; am < 2; ++am)
#pragma unroll
        for (int h = 0; h < 2; ++h) {
            float v = runmin[am][h];
            v = fminf(v, __shfl_xor_sync(0xFFFFFFFFu, v, 1));
            v = fminf(v, __shfl_xor_sync(0xFFFFFFFFu, v, 2));
            if (tq == 0)
                sMin[(warp_m * 32 + am * 16 + g + 8 * h) * 2 + warp_n] = v;
        }
    __syncthreads();
    if (tid < M_TILE) {
        float v = fminf(sMin[tid * 2], sMin[tid * 2 + 1]);
        atomicMin(&g_smin[rowBase + tid], f2o(v));
    }
}

// ---------------------------------------------------------------------------
// Rescore + finalize + LOSS (merged). Rescore body is R8-verbatim; the last
// block to finish (atomic counter) performs the loss reduction with the
// exact vq_loss code/order -> bit-identical result, deterministic.
// ---------------------------------------------------------------------------
__global__ void vq_rescore_finalize(const float* __restrict__ z,
                                    const float* __restrict__ emb,
                                    float* __restrict__ out, int out_size) {
    __shared__ float sZ[2][C_DIM];
    __shared__ u64 sBest[8];
    __shared__ u64 sFinal[2];
    __shared__ int sLast;
    int tid = threadIdx.x, lane = tid & 31, w = tid >> 5;
    int rowBlk = blockIdx.x * 2;
    if (tid < 2 * C_DIM)
        sZ[tid >> 6][tid & 63] = z[(size_t)(rowBlk + (tid >> 6)) * C_DIM + (tid & 63)];
    __syncthreads();

    int wr = w >> 2, wi = w & 3;
    int row = rowBlk + wr;
    float znorm = g_znorm[row];
    int cnt = g_cnt[row];
    const float* zr = sZ[wr];
    u64 best = 0xFFFFFFFFFFFFFFFFull;

    if (cnt <= CAP) {
        for (int i = wi * 32 + lane; i < cnt; i += 128) {
            int k = g_cand[(size_t)row * CAP + i];
            const float* e = emb + (size_t)k * C_DIM;
            float dot = 0.f;
#pragma unroll
            for (int c = 0; c < C_DIM; ++c) dot = fmaf(zr[c], e[c], dot);
            float d2 = __fadd_rn(__fsub_rn(znorm, __fmul_rn(2.0f, dot)), g_enorm[k]);
            u64 p = ((u64)f2o(d2) << 32) | (u32)k;
            best = p < best ? p : best;
        }
    } else {  // overflow fallback: exact full scan (correctness net)
        for (int k = wi * 32 + lane; k < K_CODES; k += 128) {
            const float* e = emb + (size_t)k * C_DIM;
            float dot = 0.f;
#pragma unroll
            for (int c = 0; c < C_DIM; ++c) dot = fmaf(zr[c], e[c], dot);
            float d2 = __fadd_rn(__fsub_rn(znorm, __fmul_rn(2.0f, dot)), g_enorm[k]);
            u64 p = ((u64)f2o(d2) << 32) | (u32)k;
            best = p < best ? p : best;
        }
    }
#pragma unroll
    for (int st = 16; st >= 1; st >>= 1) {
        u64 o = __shfl_xor_sync(0xFFFFFFFFu, best, st);
        best = o < best ? o : best;
    }
    if (lane == 0) sBest[w] = best;
    __syncthreads();
    if (tid < 2) {
        u64 m = sBest[tid * 4];
#pragma unroll
        for (int q = 1; q < 4; ++q) m = sBest[tid * 4 + q] < m ? sBest[tid * 4 + q] : m;
        sFinal[tid] = m;
    }
    __syncthreads();

    if (wi == 0) {
        u32 idx = (u32)sFinal[wr];
        double part = 0.0;
#pragma unroll
        for (int q = 0; q < 2; ++q) {
            int c = lane + 32 * q;
            float e = emb[(size_t)idx * C_DIM + c];
            float zv = zr[c];
            if ((size_t)row * C_DIM + c < (size_t)out_size)
                out[(size_t)row * C_DIM + c] = __fadd_rn(zv, __fsub_rn(e, zv));
            float s = __fsub_rn(zv, e);
            part += (double)__fmul_rn(s, s);
        }
#pragma unroll
        for (int st = 16; st >= 1; st >>= 1)
            part += __shfl_xor_sync(0xFFFFFFFFu, part, st);
        if (lane == 0) {
            g_rowloss[row] = part;
            if (out_size >= 133122) out[131074 + row] = (float)idx;
        }
    }

    // ---- last-block loss reduction (bit-identical to old vq_loss) ----
    __syncthreads();
    if (tid == 0) {
        __threadfence();
        u32 old = atomicAdd(&g_done_ctr, 1u);
        sLast = (old == gridDim.x - 1) ? 1 : 0;
    }
    __syncthreads();
    if (sLast) {
        __shared__ double sD[256];
        __threadfence();   // acquire: see all g_rowloss writes
        double v[8];
#pragma unroll
        for (int q = 0; q < 8; ++q) v[q] = g_rowloss[tid + 256 * q];
        double s = 0.0;
#pragma unroll
        for (int q = 0; q < 8; ++q) s += v[q];
        sD[tid] = s;
        __syncthreads();
#pragma unroll
        for (int st = 128; st >= 1; st >>= 1) {
            if (tid < st) sD[tid] += sD[tid + st];
            __syncthreads();
        }
        if (tid == 0 && out_size >= 133122) {
            float m = (float)(sD[0] / 131072.0);
            out[131072] = m;
            out[131073] = m;
        }
    }
}

// ---------------------------------------------------------------------------
extern "C" void kernel_launch(void* const* d_in, const int* in_sizes, int n_in,
                              void* d_out, int out_size) {
    const float* z = (const float*)d_in[0];
    const float* emb = (const float*)d_in[1];
    if (n_in >= 2 && in_sizes[0] == K_CODES * C_DIM && in_sizes[1] == N_ROWS * C_DIM) {
        const float* t = z; z = emb; emb = t;
    }
    float* out = (float*)d_out;

    cudaFuncSetAttribute(vq_mma_pass,
                         cudaFuncAttributeMaxDynamicSharedMemorySize, 57344);

    vq_prep<<<(K_CODES + N_ROWS) / PREP_ROWS, 256>>>(z, emb);
    vq_mma_pass<<<dim3(N_ROWS / M_TILE, NCHUNKS_SEED), 256, 57344>>>(0);
    vq_mma_pass<<<dim3(N_ROWS / M_TILE, NCHUNKS), 256, 57344>>>(1);
    vq_rescore_finalize<<<N_ROWS / 2, 256>>>(z, emb, out, out_size);
}